// round 4
// baseline (speedup 1.0000x reference)
#include <cuda_runtime.h>
#include <math.h>

// Problem constants
#define N_PTS 16384      // 128*128 spatial points
#define N_CH  512        // channels
#define NBATCH 4
#define THRV  0.01f

// ---------------- device state ----------------
__device__ float    g_invnorm[N_PTS];
__device__ float    g_nsqpart[8 * N_PTS];
__device__ float    g_dotpart[8 * 2 * N_PTS];   // [p][k][n]
__device__ float    g_cn[2 * N_CH];             // normalized centers (input to step)
__device__ float    g_centers[2 * N_CH];        // raw new centers (state)
__device__ float    g_sums[2 * N_CH];           // per-class channel sums (one writer each)
__device__ float    g_cout[2 * N_CH];           // accumulated centers over batches
__device__ float2   g_d[N_PTS];                 // state d2c
__device__ int      g_lab[N_PTS];               // state labels
__device__ unsigned g_labbits[N_PTS / 32];      // packed labels (512 words)
__device__ float2   g_dsnap[NBATCH * N_PTS];    // per-batch snapshot of d
__device__ float    g_mn[8], g_mx[8];           // per (b,k) min/max of d
__device__ float    g_cd;
__device__ float    g_cini;
__device__ int      g_Ci;
__device__ unsigned g_done;                     // last-block-done counter

__device__ __forceinline__ bool step_active(int first) {
    return first || (g_cd >= THRV && g_Ci <= 3);
}

// ---------------- init scalars + normalize centerInit ----------------
__global__ void k_init(const float* __restrict__ CI) {
    int t = threadIdx.x;   // 512
    float v0 = CI[t], v1 = CI[N_CH + t];
    float r0 = v0 * v0, r1 = v1 * v1;
    __shared__ float sm[16][2];
    for (int off = 16; off; off >>= 1) {
        r0 += __shfl_down_sync(0xffffffffu, r0, off);
        r1 += __shfl_down_sync(0xffffffffu, r1, off);
    }
    if ((t & 31) == 0) { sm[t >> 5][0] = r0; sm[t >> 5][1] = r1; }
    __syncthreads();
    __shared__ float nrm[2];
    if (t == 0) {
        float a0 = 0.f, a1 = 0.f;
        for (int i = 0; i < 16; i++) { a0 += sm[i][0]; a1 += sm[i][1]; }
        nrm[0] = fmaxf(sqrtf(a0), 1e-12f);
        nrm[1] = fmaxf(sqrtf(a1), 1e-12f);
        g_cd = 0.f; g_cini = 0.f; g_Ci = 0; g_done = 0u;
    }
    __syncthreads();
    g_cn[t] = v0 / nrm[0];
    g_cn[N_CH + t] = v1 / nrm[1];
    g_cout[t] = 0.f; g_cout[N_CH + t] = 0.f;
}

// ---------------- per-step kernel 1: partial dot products (+ nsq on first) -------
__global__ void k_dots(const float4* __restrict__ F4, int first) {
    if (!step_active(first)) return;
    __shared__ float scn0[64], scn1[64];
    int ci = blockIdx.y;                       // c-split 0..7 (64 channels each)
    int cb = ci * 64;
    int t = threadIdx.x;
    if (t < 64) { scn0[t] = g_cn[cb + t]; scn1[t] = g_cn[N_CH + cb + t]; }
    __syncthreads();
    int nq = blockIdx.x * 256 + t;             // float4 index over n (4096 total)
    float4 a0 = make_float4(0.f, 0.f, 0.f, 0.f);
    float4 a1 = make_float4(0.f, 0.f, 0.f, 0.f);
    int base = cb * 4096 + nq;
    if (first) {
        float4 ns = make_float4(0.f, 0.f, 0.f, 0.f);
#pragma unroll 8
        for (int c = 0; c < 64; c++) {
            float4 f = F4[base + c * 4096];
            float w0 = scn0[c], w1 = scn1[c];
            a0.x += f.x * w0; a0.y += f.y * w0; a0.z += f.z * w0; a0.w += f.w * w0;
            a1.x += f.x * w1; a1.y += f.y * w1; a1.z += f.z * w1; a1.w += f.w * w1;
            ns.x += f.x * f.x; ns.y += f.y * f.y; ns.z += f.z * f.z; ns.w += f.w * f.w;
        }
        ((float4*)g_nsqpart)[ci * 4096 + nq] = ns;
    } else {
#pragma unroll 16
        for (int c = 0; c < 64; c++) {
            float4 f = F4[base + c * 4096];
            float w0 = scn0[c], w1 = scn1[c];
            a0.x += f.x * w0; a0.y += f.y * w0; a0.z += f.z * w0; a0.w += f.w * w0;
            a1.x += f.x * w1; a1.y += f.y * w1; a1.z += f.z * w1; a1.w += f.w * w1;
        }
    }
    ((float4*)g_dotpart)[(ci * 2 + 0) * 4096 + nq] = a0;
    ((float4*)g_dotpart)[(ci * 2 + 1) * 4096 + nq] = a1;
}

// ---------------- per-step kernel 2: reduce partials -> d, labels, bitmask ------
__global__ void k_labels(int first) {
    if (!step_active(first)) return;
    int t = threadIdx.x;
    int n = blockIdx.x * 256 + t;
    float d0 = 0.f, d1 = 0.f;
#pragma unroll
    for (int p = 0; p < 8; p++) {
        d0 += g_dotpart[(p * 2 + 0) * N_PTS + n];
        d1 += g_dotpart[(p * 2 + 1) * N_PTS + n];
    }
    float inv;
    if (first) {
        float s = 0.f;
#pragma unroll
        for (int p = 0; p < 8; p++) s += g_nsqpart[p * N_PTS + n];
        inv = 1.f / fmaxf(sqrtf(s), 1e-12f);
        g_invnorm[n] = inv;
    } else {
        inv = g_invnorm[n];
    }
    float dd0 = 0.5f * (1.f - inv * d0);
    float dd1 = 0.5f * (1.f - inv * d1);
    int lab = (dd1 < dd0) ? 1 : 0;             // argmin; ties -> 0 (matches jnp.argmin)
    g_d[n] = make_float2(dd0, dd1);
    g_lab[n] = lab;
    unsigned m = __ballot_sync(0xffffffffu, lab);
    if ((t & 31) == 0) g_labbits[n >> 5] = m;
}

// ---------------- per-step kernel 3: per-class channel sums + fused update ------
// 512 blocks (one per channel) x 256 threads; last finishing block does the
// center update (threadfence + done-counter pattern). No float atomics anywhere.
__global__ void k_sums(const float4* __restrict__ F4, int first) {
    if (!step_active(first)) return;
    __shared__ unsigned sbits[N_PTS / 32];     // 2 KB packed labels
    int t = threadIdx.x;                       // 256
    sbits[t] = g_labbits[t];
    sbits[t + 256] = g_labbits[t + 256];
    __syncthreads();

    int c = blockIdx.x;                        // channel
    const float4* row = F4 + c * (N_PTS / 4);
    float a0 = 0.f, a1 = 0.f;
#pragma unroll
    for (int j = 0; j < 16; j++) {
        int n4 = t + j * 256;                  // float4 index
        float4 f = row[n4];
        unsigned nib = (sbits[n4 >> 3] >> ((n4 & 7) * 4)) & 15u;
        if (nib & 1u) a1 += f.x; else a0 += f.x;
        if (nib & 2u) a1 += f.y; else a0 += f.y;
        if (nib & 4u) a1 += f.z; else a0 += f.z;
        if (nib & 8u) a1 += f.w; else a0 += f.w;
    }
    // deterministic block reduction
    __shared__ float smr[8][2];
    for (int off = 16; off; off >>= 1) {
        a0 += __shfl_down_sync(0xffffffffu, a0, off);
        a1 += __shfl_down_sync(0xffffffffu, a1, off);
    }
    if ((t & 31) == 0) { smr[t >> 5][0] = a0; smr[t >> 5][1] = a1; }
    __syncthreads();
    __shared__ bool is_last;
    if (t == 0) {
        float s0 = 0.f, s1 = 0.f;
        for (int i = 0; i < 8; i++) { s0 += smr[i][0]; s1 += smr[i][1]; }
        g_sums[c] = s0;
        g_sums[N_CH + c] = s1;
        __threadfence();
        unsigned prev = atomicAdd(&g_done, 1u);
        is_last = (prev == (unsigned)(gridDim.x - 1));
    }
    __syncthreads();
    if (!is_last) return;

    // ---- fused center update (one block, 256 threads, channels t and t+256) ----
    // count of label-1 points from the bitmask already in smem
    int pc = __popc(sbits[t]) + __popc(sbits[t + 256]);
    __shared__ int smc[8];
    for (int off = 16; off; off >>= 1) pc += __shfl_down_sync(0xffffffffu, pc, off);
    if ((t & 31) == 0) smc[t >> 5] = pc;
    __syncthreads();
    __shared__ int s_c1;
    if (t == 0) {
        int s = 0;
        for (int i = 0; i < 8; i++) s += smc[i];
        s_c1 = s;
        g_done = 0u;                            // reset for next step
    }
    __syncthreads();
    int c1 = s_c1, c0 = N_PTS - c1;
    float inv0 = 1.f / (float)(c0 + 1), inv1 = 1.f / (float)(c1 + 1);

    int ca = t, cb2 = t + 256;
    float nc0a = g_sums[ca] * inv0,          nc0b = g_sums[cb2] * inv0;
    float nc1a = g_sums[N_CH + ca] * inv1,   nc1b = g_sums[N_CH + cb2] * inv1;
    float o0a = g_cn[ca], o0b = g_cn[cb2];
    float o1a = g_cn[N_CH + ca], o1b = g_cn[N_CH + cb2];
    g_centers[ca] = nc0a;        g_centers[cb2] = nc0b;
    g_centers[N_CH + ca] = nc1a; g_centers[N_CH + cb2] = nc1b;

    float r0 = nc0a * nc0a + nc0b * nc0b;      // ||nc0||^2 partial
    float r1 = nc1a * nc1a + nc1b * nc1b;      // ||nc1||^2 partial
    float r2 = nc0a * o0a + nc0b * o0b;        // nc0 . old_cn0 partial
    float r3 = nc1a * o1a + nc1b * o1b;        // nc1 . old_cn1 partial
    __shared__ float smu[8][4];
    for (int off = 16; off; off >>= 1) {
        r0 += __shfl_down_sync(0xffffffffu, r0, off);
        r1 += __shfl_down_sync(0xffffffffu, r1, off);
        r2 += __shfl_down_sync(0xffffffffu, r2, off);
        r3 += __shfl_down_sync(0xffffffffu, r3, off);
    }
    if ((t & 31) == 0) { smu[t >> 5][0] = r0; smu[t >> 5][1] = r1; smu[t >> 5][2] = r2; smu[t >> 5][3] = r3; }
    __syncthreads();
    __shared__ float bro[2];
    if (t == 0) {
        float b0 = 0.f, b1 = 0.f, b2 = 0.f, b3 = 0.f;
        for (int i = 0; i < 8; i++) { b0 += smu[i][0]; b1 += smu[i][1]; b2 += smu[i][2]; b3 += smu[i][3]; }
        float nn0 = fmaxf(sqrtf(b0), 1e-12f);
        float nn1 = fmaxf(sqrtf(b1), 1e-12f);
        float cd = 0.5f * (b2 / nn0 + b3 / nn1);
        if (g_Ci == 0) g_cini += cd;
        g_Ci = g_Ci + 1;
        g_cd = cd;
        bro[0] = nn0; bro[1] = nn1;
    }
    __syncthreads();
    float in0 = 1.f / bro[0], in1 = 1.f / bro[1];
    g_cn[ca] = nc0a * in0;        g_cn[cb2] = nc0b * in0;
    g_cn[N_CH + ca] = nc1a * in1; g_cn[N_CH + cb2] = nc1b * in1;
}

// ---------------- batch snapshot ----------------
__global__ void k_snapshot(int b, float* __restrict__ out) {
    int t = threadIdx.x;
    int n = blockIdx.x * 256 + t;
    int lab = g_lab[n];
    g_dsnap[(b << 14) + n] = g_d[n];
    out[1024 + (b << 14) + n] = (float)lab;                    // labels
    int ohb = 66560 + (((b << 14) + n) << 1);                  // one-hot
    out[ohb]     = lab ? 0.f : 1.f;
    out[ohb + 1] = lab ? 1.f : 0.f;
    if (blockIdx.x == 0) {
        for (int i = t; i < 2 * N_CH; i += 256) g_cout[i] += g_centers[i];
        if (t == 0) g_Ci = 0;                                   // batch boundary reset
    }
}

// ---------------- per-(batch,class) min/max of snapshot d ----------------
__global__ void k_minmax() {
    int b = blockIdx.x >> 1, k = blockIdx.x & 1;
    int t = threadIdx.x;
    float mn = 3.4e38f, mx = -3.4e38f;
    for (int i = t; i < N_PTS; i += 256) {
        float2 dv = g_dsnap[(b << 14) + i];
        float v = k ? dv.y : dv.x;
        mn = fminf(mn, v); mx = fmaxf(mx, v);
    }
    __shared__ float smn[8], smx[8];
    for (int off = 16; off; off >>= 1) {
        mn = fminf(mn, __shfl_down_sync(0xffffffffu, mn, off));
        mx = fmaxf(mx, __shfl_down_sync(0xffffffffu, mx, off));
    }
    if ((t & 31) == 0) { smn[t >> 5] = mn; smx[t >> 5] = mx; }
    __syncthreads();
    if (t == 0) {
        for (int i = 1; i < 8; i++) { mn = fminf(mn, smn[i]); mx = fmaxf(mx, smx[i]); }
        g_mn[blockIdx.x] = mn; g_mx[blockIdx.x] = mx;
    }
}

// ---------------- final: weight, centers-out, cinidist ----------------
__global__ void k_final(float* __restrict__ out) {
    int idx = blockIdx.x * 256 + threadIdx.x;   // 65536 = 4*16384
    int b = idx >> 14;
    int lab = (int)out[1024 + idx];
    float2 dv = g_dsnap[idx];
    float d = lab ? dv.y : dv.x;
    float rng = g_mx[b * 2 + lab] - g_mn[b * 2 + lab] + 1e-7f;
    out[197632 + idx] = 1.1f + d / rng;         // weight = (1 - (-d/rng)) + 0.1
    if (idx < 2 * N_CH) out[idx] = g_cout[idx] * 0.25f;        // centersIterout
    if (idx == 0) out[263168] = g_cini * 0.25f;                // cinidist
}

// ---------------- launch ----------------
extern "C" void kernel_launch(void* const* d_in, const int* in_sizes, int n_in,
                              void* d_out, int out_size) {
    const float* F  = (const float*)d_in[0];   // FeatureT [4,512,128,128]
    const float* CI = (const float*)d_in[1];   // centerInit [2,512]
    if (n_in >= 2 && in_sizes[0] < in_sizes[1]) {  // defensive: identify by size
        const float* tmp = F; F = CI; CI = tmp;
    }
    float* out = (float*)d_out;
    (void)out_size;

    // init scalar state + normalized centerInit
    k_init<<<1, 512>>>(CI);

    // 17 steps: s=0 unconditional (centersIter is None), s=1..16 masked (4 per batch)
    for (int s = 0; s < 17; s++) {
        int first = (s == 0) ? 1 : 0;
        k_dots<<<dim3(16, 8), 256>>>((const float4*)F, first);
        k_labels<<<64, 256>>>(first);
        k_sums<<<512, 256>>>((const float4*)F, first);
        if (s > 0 && (s & 3) == 0) {
            k_snapshot<<<64, 256>>>(s / 4 - 1, out);
        }
    }

    k_minmax<<<8, 256>>>();
    k_final<<<256, 256>>>(out);
}